// round 1
// baseline (speedup 1.0000x reference)
#include <cuda_runtime.h>
#include <math.h>

// ---------------------------------------------------------------------------
// HierarchicalReversibleAttention — fp32 baseline
// B=2, S=2048, D=512, H=8, hd=64. Levels pool->proj->pos->interp->attn(mask)->wo
// Fusion: concat(outs) -> qkv(1536) -> attn(hd=192) -> fus_out -> out proj + LN
// Outputs: d_out[0 .. 2097151] = output, d_out[2097152 .. ] = coupling
// ---------------------------------------------------------------------------

#define D_MODEL 512
#define SEQ     2048
#define BATCH   2
#define MROWS   (BATCH * SEQ)   // 4096
#define NHEADS  8

// -------------------- device scratch (static, no allocation) ---------------
__device__ float g_feat[(size_t)3 * MROWS * D_MODEL];   // interpolated feats per level
__device__ float g_cat [(size_t)MROWS * 1536];          // concat of level outputs
__device__ float g_q   [(size_t)MROWS * 1536];
__device__ float g_k   [(size_t)MROWS * 1536];
__device__ float g_v   [(size_t)MROWS * 1536];
__device__ float g_t1  [(size_t)MROWS * 1536];
__device__ float g_t2  [(size_t)MROWS * 1536];
__device__ float g_pool[(size_t)BATCH * 512 * D_MODEL];
__device__ float g_fp  [(size_t)BATCH * 512 * D_MODEL];

// -------------------- helpers ----------------------------------------------
__device__ __forceinline__ bool is_global_pos(int j) {
    // jnp.linspace(0, 2047, 32) in f32, truncated: {0, 66, 132, ..., 1980, 2047}
    return (j == 2047) || ((j % 66 == 0) && (j <= 1980));
}

// -------------------- pooling ----------------------------------------------
__global__ void pool_kernel(const float* __restrict__ x, float* __restrict__ out,
                            int P, int r) {
    int idx = blockIdx.x * blockDim.x + threadIdx.x;
    int total = BATCH * P * D_MODEL;
    if (idx >= total) return;
    int d = idx & (D_MODEL - 1);
    int p = (idx >> 9) % P;
    int b = idx / (D_MODEL * P);
    const float* src = x + ((size_t)b * SEQ + (size_t)p * r) * D_MODEL + d;
    float s = 0.f;
    for (int t = 0; t < r; t++) s += src[(size_t)t * D_MODEL];
    out[idx] = s * (1.0f / (float)r);
}

// -------------------- linear interpolation (upsample) ----------------------
__global__ void interp_kernel(const float* __restrict__ in, float* __restrict__ out,
                              int P) {
    int idx = blockIdx.x * blockDim.x + threadIdx.x;
    if (idx >= MROWS * D_MODEL) return;
    int d = idx & (D_MODEL - 1);
    int s = (idx >> 9) & (SEQ - 1);
    int b = idx >> 20;   // 2048*512 = 2^20
    float scale = (float)P / (float)SEQ;          // power of two: exact
    float src = ((float)s + 0.5f) * scale - 0.5f;
    float flr = floorf(src);
    float f = src - flr;
    int i0 = (int)flr;
    int a = i0 < 0 ? 0 : (i0 > P - 1 ? P - 1 : i0);
    int c = (i0 + 1) < 0 ? 0 : ((i0 + 1) > P - 1 ? P - 1 : i0 + 1);
    const float* base = in + (size_t)b * P * D_MODEL + d;
    out[idx] = (1.0f - f) * base[(size_t)a * D_MODEL] + f * base[(size_t)c * D_MODEL];
}

// -------------------- GEMM: C = A @ W^T (+bias)(+pos)(+res) ---------------
// A: [M,K] (lda), W: [N,K] row-major, C: [M,N] (ldc)
__global__ __launch_bounds__(256)
void gemm_bt_kernel(const float* __restrict__ A, int lda,
                    const float* __restrict__ W,
                    const float* __restrict__ bias,
                    const float* __restrict__ pos, int posP,
                    const float* __restrict__ res, int ldres,
                    float* __restrict__ C, int ldc,
                    int M, int N, int K) {
    const int BM = 64, BN = 64, BK = 16;
    __shared__ float As[BK][BM + 1];
    __shared__ float Ws[BK][BN + 1];
    int bm = blockIdx.y * BM;
    int bn = blockIdx.x * BN;
    int tid = threadIdx.x;
    int tx = tid & 15, ty = tid >> 4;

    float acc[4][4];
#pragma unroll
    for (int i = 0; i < 4; i++)
#pragma unroll
        for (int j = 0; j < 4; j++) acc[i][j] = 0.f;

    for (int k0 = 0; k0 < K; k0 += BK) {
#pragma unroll
        for (int it = 0; it < 4; it++) {
            int i = tid + it * 256;
            int r = i >> 4, c = i & 15;
            As[c][r] = A[(size_t)(bm + r) * lda + k0 + c];
        }
#pragma unroll
        for (int it = 0; it < 4; it++) {
            int i = tid + it * 256;
            int r = i >> 4, c = i & 15;
            Ws[c][r] = W[(size_t)(bn + r) * K + k0 + c];
        }
        __syncthreads();
#pragma unroll
        for (int kk = 0; kk < BK; kk++) {
            float a[4], b[4];
#pragma unroll
            for (int i = 0; i < 4; i++) a[i] = As[kk][ty * 4 + i];
#pragma unroll
            for (int j = 0; j < 4; j++) b[j] = Ws[kk][tx * 4 + j];
#pragma unroll
            for (int i = 0; i < 4; i++)
#pragma unroll
                for (int j = 0; j < 4; j++) acc[i][j] += a[i] * b[j];
        }
        __syncthreads();
    }
#pragma unroll
    for (int i = 0; i < 4; i++) {
        int m = bm + ty * 4 + i;
#pragma unroll
        for (int j = 0; j < 4; j++) {
            int n = bn + tx * 4 + j;
            float v = acc[i][j];
            if (bias) v += bias[n];
            if (pos)  v += pos[(size_t)(m % posP) * N + n];
            if (res)  v += res[(size_t)m * ldres + n];
            C[(size_t)m * ldc + n] = v;
        }
    }
}

// -------------------- flash attention --------------------------------------
// MASK: 0 = local window, 1 = local|strided, 2 = global positions, 3 = none
template<int HD, int MASK>
__global__ __launch_bounds__(256)
void flash_kernel(const float* __restrict__ Q, const float* __restrict__ K,
                  const float* __restrict__ V, float* __restrict__ O,
                  int Dtot, float scale) {
    const int TQ = 64, TK = 64;
    const int NG = HD / 64;
    const int LDQ = HD + 1;
    const int LDS_S = TK + 1;
    extern __shared__ float sm[];
    float* Qs = sm;
    float* Ks = Qs + TQ * LDQ;
    float* Vs = Ks + TK * LDQ;
    float* Ss = Vs + TK * LDQ;
    float* mrow = Ss + TQ * LDS_S;
    float* lrow = mrow + TQ;
    float* crow = lrow + TQ;

    int q0 = blockIdx.x * TQ;
    int h  = blockIdx.y;
    int b  = blockIdx.z;
    int tid = threadIdx.x;
    int tx = tid & 15, ty = tid >> 4;

    const float* Qb = Q + (size_t)b * SEQ * Dtot + h * HD;
    const float* Kb = K + (size_t)b * SEQ * Dtot + h * HD;
    const float* Vb = V + (size_t)b * SEQ * Dtot + h * HD;

    for (int i = tid; i < TQ * HD; i += 256) {
        int r = i / HD, c = i % HD;
        Qs[r * LDQ + c] = Qb[(size_t)(q0 + r) * Dtot + c];
    }
    if (tid < TQ) { mrow[tid] = -INFINITY; lrow[tid] = 0.f; }
    float acc[4][NG * 4];
#pragma unroll
    for (int i = 0; i < 4; i++)
#pragma unroll
        for (int j = 0; j < NG * 4; j++) acc[i][j] = 0.f;
    __syncthreads();

    for (int k0 = 0; k0 < SEQ; k0 += TK) {
        if (MASK == 0) {
            // tile fully outside local window -> skip
            if (k0 > q0 + 63 + 256 || k0 + 63 < q0 - 256) continue;
        }
        for (int i = tid; i < TK * HD; i += 256) {
            int r = i / HD, c = i % HD;
            Ks[r * LDQ + c] = Kb[(size_t)(k0 + r) * Dtot + c];
            Vs[r * LDQ + c] = Vb[(size_t)(k0 + r) * Dtot + c];
        }
        __syncthreads();

        float sacc[4][4];
#pragma unroll
        for (int i = 0; i < 4; i++)
#pragma unroll
            for (int j = 0; j < 4; j++) sacc[i][j] = 0.f;
        for (int kk = 0; kk < HD; kk++) {
            float a[4], bb[4];
#pragma unroll
            for (int i = 0; i < 4; i++) a[i] = Qs[(ty * 4 + i) * LDQ + kk];
#pragma unroll
            for (int j = 0; j < 4; j++) bb[j] = Ks[(tx * 4 + j) * LDQ + kk];
#pragma unroll
            for (int i = 0; i < 4; i++)
#pragma unroll
                for (int j = 0; j < 4; j++) sacc[i][j] += a[i] * bb[j];
        }
#pragma unroll
        for (int i = 0; i < 4; i++) {
            int gi_ = q0 + ty * 4 + i;
#pragma unroll
            for (int j = 0; j < 4; j++) {
                int gj = k0 + tx * 4 + j;
                float sv = sacc[i][j] * scale;
                bool ok;
                if      (MASK == 0) { int dd = gi_ - gj; ok = (dd <= 256 && dd >= -256); }
                else if (MASK == 1) { int dd = gi_ - gj; ok = (dd <= 256 && dd >= -256) || ((gj & 15) == 0); }
                else if (MASK == 2) { ok = is_global_pos(gi_) || is_global_pos(gj); }
                else ok = true;
                Ss[(ty * 4 + i) * LDS_S + tx * 4 + j] = ok ? sv : -1e9f;
            }
        }
        __syncthreads();

        if (tid < TQ) {
            float mo = mrow[tid];
            float mx = mo;
            float* srow = Ss + tid * LDS_S;
            for (int j = 0; j < TK; j++) mx = fmaxf(mx, srow[j]);
            float cf = expf(mo - mx);    // mo=-inf -> 0
            float sum = 0.f;
            for (int j = 0; j < TK; j++) {
                float p = expf(srow[j] - mx);
                srow[j] = p;
                sum += p;
            }
            mrow[tid] = mx;
            lrow[tid] = lrow[tid] * cf + sum;
            crow[tid] = cf;
        }
        __syncthreads();

#pragma unroll
        for (int i = 0; i < 4; i++) {
            float cf = crow[ty * 4 + i];
#pragma unroll
            for (int j = 0; j < NG * 4; j++) acc[i][j] *= cf;
        }
        for (int kk = 0; kk < TK; kk++) {
            float p[4];
#pragma unroll
            for (int i = 0; i < 4; i++) p[i] = Ss[(ty * 4 + i) * LDS_S + kk];
#pragma unroll
            for (int g = 0; g < NG; g++) {
#pragma unroll
                for (int j = 0; j < 4; j++) {
                    float vv = Vs[kk * LDQ + g * 64 + tx * 4 + j];
#pragma unroll
                    for (int i = 0; i < 4; i++) acc[i][g * 4 + j] += p[i] * vv;
                }
            }
        }
        __syncthreads();
    }

#pragma unroll
    for (int i = 0; i < 4; i++) {
        float inv = 1.0f / lrow[ty * 4 + i];
        size_t base = (size_t)(b * SEQ + q0 + ty * 4 + i) * Dtot + h * HD;
#pragma unroll
        for (int g = 0; g < NG; g++)
#pragma unroll
            for (int j = 0; j < 4; j++)
                O[base + g * 64 + tx * 4 + j] = acc[i][g * 4 + j] * inv;
    }
}

// -------------------- coupling ---------------------------------------------
__global__ void coupling_kernel(const float* __restrict__ feat,
                                const float* __restrict__ cat_,
                                float* __restrict__ out) {
    int idx = blockIdx.x * blockDim.x + threadIdx.x;
    if (idx >= MROWS * D_MODEL) return;
    int m = idx >> 9, d = idx & 511;
    float s = 0.f;
#pragma unroll
    for (int l = 0; l < 3; l++)
        s += feat[(size_t)l * MROWS * D_MODEL + idx] + cat_[(size_t)m * 1536 + l * 512 + d];
    out[idx] = s * (1.0f / 3.0f);
}

// -------------------- layernorm --------------------------------------------
__global__ __launch_bounds__(256)
void ln_kernel(const float* __restrict__ in, const float* __restrict__ g,
               const float* __restrict__ b, float* __restrict__ out) {
    __shared__ float red[256];
    int row = blockIdx.x;
    int tid = threadIdx.x;
    const float* xr = in + (size_t)row * D_MODEL;
    float v0 = xr[tid], v1 = xr[tid + 256];
    red[tid] = v0 + v1;
    __syncthreads();
    for (int o = 128; o > 0; o >>= 1) {
        if (tid < o) red[tid] += red[tid + o];
        __syncthreads();
    }
    float mu = red[0] * (1.0f / 512.0f);
    __syncthreads();
    float d0 = v0 - mu, d1 = v1 - mu;
    red[tid] = d0 * d0 + d1 * d1;
    __syncthreads();
    for (int o = 128; o > 0; o >>= 1) {
        if (tid < o) red[tid] += red[tid + o];
        __syncthreads();
    }
    float var = red[0] * (1.0f / 512.0f);
    float inv = rsqrtf(var + 1e-5f);
    out[(size_t)row * D_MODEL + tid]       = d0 * inv * g[tid] + b[tid];
    out[(size_t)row * D_MODEL + tid + 256] = d1 * inv * g[tid + 256] + b[tid + 256];
}

// -------------------- host side --------------------------------------------
static void gemm(const float* A, int lda, const float* W, const float* bias,
                 const float* pos, int posP, const float* res, int ldres,
                 float* C, int ldc, int M, int N, int K) {
    dim3 grid(N / 64, M / 64);
    gemm_bt_kernel<<<grid, 256>>>(A, lda, W, bias, pos, posP, res, ldres, C, ldc, M, N, K);
}

extern "C" void kernel_launch(void* const* d_in, const int* in_sizes, int n_in,
                              void* d_out, int out_size) {
    const float* x      = (const float*)d_in[0];
    const float* proj_w = (const float*)d_in[1];
    const float* proj_b = (const float*)d_in[2];
    const float* pos_e  = (const float*)d_in[3];
    const float* wq     = (const float*)d_in[4];
    const float* bq     = (const float*)d_in[5];
    const float* wk     = (const float*)d_in[6];
    const float* bk     = (const float*)d_in[7];
    const float* wv     = (const float*)d_in[8];
    const float* bv     = (const float*)d_in[9];
    const float* wo     = (const float*)d_in[10];
    const float* bo     = (const float*)d_in[11];
    const float* fin_w  = (const float*)d_in[12];
    const float* fin_b  = (const float*)d_in[13];
    const float* fout_w = (const float*)d_in[14];
    const float* fout_b = (const float*)d_in[15];
    const float* outp_w = (const float*)d_in[16];
    const float* outp_b = (const float*)d_in[17];
    const float* ln_g   = (const float*)d_in[18];
    const float* ln_b   = (const float*)d_in[19];
    float* out = (float*)d_out;

    float *feat, *cat_, *q, *k, *v, *t1, *t2, *pool, *fp;
    cudaGetSymbolAddress((void**)&feat, g_feat);
    cudaGetSymbolAddress((void**)&cat_, g_cat);
    cudaGetSymbolAddress((void**)&q,    g_q);
    cudaGetSymbolAddress((void**)&k,    g_k);
    cudaGetSymbolAddress((void**)&v,    g_v);
    cudaGetSymbolAddress((void**)&t1,   g_t1);
    cudaGetSymbolAddress((void**)&t2,   g_t2);
    cudaGetSymbolAddress((void**)&pool, g_pool);
    cudaGetSymbolAddress((void**)&fp,   g_fp);

    const int SMEM_LVL = (3 * 64 * 65 + 64 * 65 + 3 * 64) * 4;    // 67,328 B
    const int SMEM_FUS = (3 * 64 * 193 + 64 * 65 + 3 * 64) * 4;   // 165,632 B
    cudaFuncSetAttribute((const void*)flash_kernel<64, 0>, cudaFuncAttributeMaxDynamicSharedMemorySize, SMEM_LVL);
    cudaFuncSetAttribute((const void*)flash_kernel<64, 1>, cudaFuncAttributeMaxDynamicSharedMemorySize, SMEM_LVL);
    cudaFuncSetAttribute((const void*)flash_kernel<64, 2>, cudaFuncAttributeMaxDynamicSharedMemorySize, SMEM_LVL);
    cudaFuncSetAttribute((const void*)flash_kernel<192, 3>, cudaFuncAttributeMaxDynamicSharedMemorySize, SMEM_FUS);

    const int POOLP[3] = {512, 128, 32};
    dim3 fgrid(SEQ / 64, NHEADS, BATCH);

    for (int l = 0; l < 3; l++) {
        int P = POOLP[l];
        int r = SEQ / P;
        int BP = BATCH * P;
        // pool
        pool_kernel<<<(BP * D_MODEL + 255) / 256, 256>>>(x, pool, P, r);
        // proj + bias + pos_emb
        gemm(pool, D_MODEL, proj_w + (size_t)l * D_MODEL * D_MODEL,
             proj_b + (size_t)l * D_MODEL,
             pos_e + (size_t)l * 10000 * D_MODEL, P,
             nullptr, 0, fp, D_MODEL, BP, D_MODEL, D_MODEL);
        // upsample
        float* fl = feat + (size_t)l * MROWS * D_MODEL;
        interp_kernel<<<(MROWS * D_MODEL + 255) / 256, 256>>>(fp, fl, P);
        // q/k/v
        gemm(fl, D_MODEL, wq + (size_t)l * D_MODEL * D_MODEL, bq + (size_t)l * D_MODEL,
             nullptr, 0, nullptr, 0, q, D_MODEL, MROWS, D_MODEL, D_MODEL);
        gemm(fl, D_MODEL, wk + (size_t)l * D_MODEL * D_MODEL, bk + (size_t)l * D_MODEL,
             nullptr, 0, nullptr, 0, k, D_MODEL, MROWS, D_MODEL, D_MODEL);
        gemm(fl, D_MODEL, wv + (size_t)l * D_MODEL * D_MODEL, bv + (size_t)l * D_MODEL,
             nullptr, 0, nullptr, 0, v, D_MODEL, MROWS, D_MODEL, D_MODEL);
        // attention
        float scale = 0.125f;  // 1/sqrt(64)
        if (l == 0)
            flash_kernel<64, 0><<<fgrid, 256, SMEM_LVL>>>(q, k, v, t1, D_MODEL, scale);
        else if (l == 1)
            flash_kernel<64, 1><<<fgrid, 256, SMEM_LVL>>>(q, k, v, t1, D_MODEL, scale);
        else
            flash_kernel<64, 2><<<fgrid, 256, SMEM_LVL>>>(q, k, v, t1, D_MODEL, scale);
        // out projection -> concat slot
        gemm(t1, D_MODEL, wo + (size_t)l * D_MODEL * D_MODEL, bo + (size_t)l * D_MODEL,
             nullptr, 0, nullptr, 0, cat_ + (size_t)l * D_MODEL, 1536, MROWS, D_MODEL, D_MODEL);
    }

    // coupling = mean_l(feat_l + out_l) -> second half of d_out
    coupling_kernel<<<(MROWS * D_MODEL + 255) / 256, 256>>>(feat, cat_, out + (size_t)MROWS * D_MODEL);

    // fusion qkv (rows of fus_in_w)
    gemm(cat_, 1536, fin_w,                         fin_b,        nullptr, 0, nullptr, 0, q, 1536, MROWS, 1536, 1536);
    gemm(cat_, 1536, fin_w + (size_t)1536 * 1536,   fin_b + 1536, nullptr, 0, nullptr, 0, k, 1536, MROWS, 1536, 1536);
    gemm(cat_, 1536, fin_w + (size_t)2 * 1536 * 1536, fin_b + 3072, nullptr, 0, nullptr, 0, v, 1536, MROWS, 1536, 1536);
    // fusion attention, hd=192
    flash_kernel<192, 3><<<fgrid, 256, SMEM_FUS>>>(q, k, v, t1, 1536, 1.0f / sqrtf(192.0f));
    // fus_out
    gemm(t1, 1536, fout_w, fout_b, nullptr, 0, nullptr, 0, t2, 1536, MROWS, 1536, 1536);
    // out proj + residual x
    gemm(t2, 1536, outp_w, outp_b, nullptr, 0, x, D_MODEL, t1, D_MODEL, MROWS, D_MODEL, 1536);
    // layernorm -> first half of d_out
    ln_kernel<<<MROWS, 256>>>(t1, ln_g, ln_b, out);
}

// round 3
// speedup vs baseline: 1.2890x; 1.2890x over previous
#include <cuda_runtime.h>
#include <math.h>

// ---------------------------------------------------------------------------
// HierarchicalReversibleAttention — R3 (= R2 resubmit after infra flake):
// 128x128 8x8-microtile fp32 GEMM
// ---------------------------------------------------------------------------

#define D_MODEL 512
#define SEQ     2048
#define BATCH   2
#define MROWS   (BATCH * SEQ)   // 4096
#define NHEADS  8

// -------------------- device scratch (static, no allocation) ---------------
__device__ float g_feat[(size_t)3 * MROWS * D_MODEL];
__device__ float g_cat [(size_t)MROWS * 1536];
__device__ float g_q   [(size_t)MROWS * 1536];
__device__ float g_k   [(size_t)MROWS * 1536];
__device__ float g_v   [(size_t)MROWS * 1536];
__device__ float g_t1  [(size_t)MROWS * 1536];
__device__ float g_t2  [(size_t)MROWS * 1536];
__device__ float g_pool[(size_t)BATCH * 512 * D_MODEL];
__device__ float g_fp  [(size_t)BATCH * 512 * D_MODEL];

// -------------------- helpers ----------------------------------------------
__device__ __forceinline__ bool is_global_pos(int j) {
    return (j == 2047) || ((j % 66 == 0) && (j <= 1980));
}

// -------------------- pooling ----------------------------------------------
__global__ void pool_kernel(const float* __restrict__ x, float* __restrict__ out,
                            int P, int r) {
    int idx = blockIdx.x * blockDim.x + threadIdx.x;
    int total = BATCH * P * D_MODEL;
    if (idx >= total) return;
    int d = idx & (D_MODEL - 1);
    int p = (idx >> 9) % P;
    int b = idx / (D_MODEL * P);
    const float* src = x + ((size_t)b * SEQ + (size_t)p * r) * D_MODEL + d;
    float s = 0.f;
    for (int t = 0; t < r; t++) s += src[(size_t)t * D_MODEL];
    out[idx] = s * (1.0f / (float)r);
}

// -------------------- linear interpolation (upsample) ----------------------
__global__ void interp_kernel(const float* __restrict__ in, float* __restrict__ out,
                              int P) {
    int idx = blockIdx.x * blockDim.x + threadIdx.x;
    if (idx >= MROWS * D_MODEL) return;
    int d = idx & (D_MODEL - 1);
    int s = (idx >> 9) & (SEQ - 1);
    int b = idx >> 20;
    float scale = (float)P / (float)SEQ;
    float src = ((float)s + 0.5f) * scale - 0.5f;
    float flr = floorf(src);
    float f = src - flr;
    int i0 = (int)flr;
    int a = i0 < 0 ? 0 : (i0 > P - 1 ? P - 1 : i0);
    int c = (i0 + 1) < 0 ? 0 : ((i0 + 1) > P - 1 ? P - 1 : i0 + 1);
    const float* base = in + (size_t)b * P * D_MODEL + d;
    out[idx] = (1.0f - f) * base[(size_t)a * D_MODEL] + f * base[(size_t)c * D_MODEL];
}

// -------------------- small GEMM (64x64, for proj M<128) -------------------
__global__ __launch_bounds__(256)
void gemm64_kernel(const float* __restrict__ A, int lda,
                   const float* __restrict__ W,
                   const float* __restrict__ bias,
                   const float* __restrict__ pos, int posP,
                   float* __restrict__ C, int ldc,
                   int M, int N, int K) {
    const int BM = 64, BN = 64, BK = 16;
    __shared__ float As[BK][BM + 1];
    __shared__ float Ws[BK][BN + 1];
    int bm = blockIdx.y * BM;
    int bn = blockIdx.x * BN;
    int tid = threadIdx.x;
    int tx = tid & 15, ty = tid >> 4;

    float acc[4][4];
#pragma unroll
    for (int i = 0; i < 4; i++)
#pragma unroll
        for (int j = 0; j < 4; j++) acc[i][j] = 0.f;

    for (int k0 = 0; k0 < K; k0 += BK) {
#pragma unroll
        for (int it = 0; it < 4; it++) {
            int i = tid + it * 256;
            int r = i >> 4, c = i & 15;
            As[c][r] = A[(size_t)(bm + r) * lda + k0 + c];
        }
#pragma unroll
        for (int it = 0; it < 4; it++) {
            int i = tid + it * 256;
            int r = i >> 4, c = i & 15;
            Ws[c][r] = W[(size_t)(bn + r) * K + k0 + c];
        }
        __syncthreads();
#pragma unroll
        for (int kk = 0; kk < BK; kk++) {
            float a[4], b[4];
#pragma unroll
            for (int i = 0; i < 4; i++) a[i] = As[kk][ty * 4 + i];
#pragma unroll
            for (int j = 0; j < 4; j++) b[j] = Ws[kk][tx * 4 + j];
#pragma unroll
            for (int i = 0; i < 4; i++)
#pragma unroll
                for (int j = 0; j < 4; j++) acc[i][j] += a[i] * b[j];
        }
        __syncthreads();
    }
#pragma unroll
    for (int i = 0; i < 4; i++) {
        int m = bm + ty * 4 + i;
#pragma unroll
        for (int j = 0; j < 4; j++) {
            int n = bn + tx * 4 + j;
            float v = acc[i][j];
            if (bias) v += bias[n];
            if (pos)  v += pos[(size_t)(m % posP) * N + n];
            C[(size_t)m * ldc + n] = v;
        }
    }
}

// -------------------- big GEMM: 128x128x16, 8x8 microtile ------------------
// C = A @ W^T (+bias)(+res).  A:[M,K] lda, W:[N,K], C:[M,N] ldc.
// M % 128 == 0, N % 128 == 0, K % 16 == 0.
#define LDS_T 132
__global__ __launch_bounds__(256)
void gemm128_kernel(const float* __restrict__ A, int lda,
                    const float* __restrict__ W,
                    const float* __restrict__ bias,
                    const float* __restrict__ res, int ldres,
                    float* __restrict__ C, int ldc,
                    int M, int N, int K) {
    __shared__ float As[16][LDS_T];
    __shared__ float Ws[16][LDS_T];

    int bm = blockIdx.y * 128;
    int bn = blockIdx.x * 128;
    int tid = threadIdx.x;
    int warp = tid >> 5, lane = tid & 31;
    int warp_m = warp >> 1;          // 0..3  -> 32 rows each
    int warp_n = warp & 1;           // 0..1  -> 64 cols each
    int lm = lane >> 3;              // 0..3
    int ln = lane & 7;               // 0..7

    int r0 = tid >> 2;               // 0..63  (row, first half)
    int kq = (tid & 3) << 2;         // 0,4,8,12

    float acc[2][2][4][4];
#pragma unroll
    for (int mh = 0; mh < 2; mh++)
#pragma unroll
        for (int nh = 0; nh < 2; nh++)
#pragma unroll
            for (int i = 0; i < 4; i++)
#pragma unroll
                for (int j = 0; j < 4; j++) acc[mh][nh][i][j] = 0.f;

    const int m_base = bm + warp_m * 32 + lm * 4;
    const int n_base = bn + warp_n * 64 + ln * 4;

    for (int k0 = 0; k0 < K; k0 += 16) {
#pragma unroll
        for (int half = 0; half < 2; half++) {
            int r = r0 + half * 64;
            float4 av = *(const float4*)&A[(size_t)(bm + r) * lda + k0 + kq];
            As[kq + 0][r] = av.x; As[kq + 1][r] = av.y;
            As[kq + 2][r] = av.z; As[kq + 3][r] = av.w;
            float4 wv = *(const float4*)&W[(size_t)(bn + r) * K + k0 + kq];
            Ws[kq + 0][r] = wv.x; Ws[kq + 1][r] = wv.y;
            Ws[kq + 2][r] = wv.z; Ws[kq + 3][r] = wv.w;
        }
        __syncthreads();

#pragma unroll
        for (int kk = 0; kk < 16; kk++) {
            float4 a0 = *(const float4*)&As[kk][warp_m * 32 + lm * 4];
            float4 a1 = *(const float4*)&As[kk][warp_m * 32 + 16 + lm * 4];
            float4 b0 = *(const float4*)&Ws[kk][warp_n * 64 + ln * 4];
            float4 b1 = *(const float4*)&Ws[kk][warp_n * 64 + 32 + ln * 4];
            float av[2][4] = {{a0.x, a0.y, a0.z, a0.w}, {a1.x, a1.y, a1.z, a1.w}};
            float bv[2][4] = {{b0.x, b0.y, b0.z, b0.w}, {b1.x, b1.y, b1.z, b1.w}};
#pragma unroll
            for (int mh = 0; mh < 2; mh++)
#pragma unroll
                for (int nh = 0; nh < 2; nh++)
#pragma unroll
                    for (int i = 0; i < 4; i++)
#pragma unroll
                        for (int j = 0; j < 4; j++)
                            acc[mh][nh][i][j] += av[mh][i] * bv[nh][j];
        }
        __syncthreads();
    }

#pragma unroll
    for (int mh = 0; mh < 2; mh++) {
#pragma unroll
        for (int i = 0; i < 4; i++) {
            int m = m_base + mh * 16 + i;
#pragma unroll
            for (int nh = 0; nh < 2; nh++) {
                int n = n_base + nh * 32;
                float4 v;
                v.x = acc[mh][nh][i][0]; v.y = acc[mh][nh][i][1];
                v.z = acc[mh][nh][i][2]; v.w = acc[mh][nh][i][3];
                if (bias) {
                    v.x += bias[n + 0]; v.y += bias[n + 1];
                    v.z += bias[n + 2]; v.w += bias[n + 3];
                }
                if (res) {
                    const float* rr = &res[(size_t)m * ldres + n];
                    v.x += rr[0]; v.y += rr[1]; v.z += rr[2]; v.w += rr[3];
                }
                *(float4*)&C[(size_t)m * ldc + n] = v;
            }
        }
    }
}

// -------------------- flash attention --------------------------------------
template<int HD, int MASK>
__global__ __launch_bounds__(256)
void flash_kernel(const float* __restrict__ Q, const float* __restrict__ K,
                  const float* __restrict__ V, float* __restrict__ O,
                  int Dtot, float scale) {
    const int TQ = 64, TK = 64;
    const int NG = HD / 64;
    const int LDQ = HD + 1;
    const int LDS_S = TK + 1;
    extern __shared__ float sm[];
    float* Qs = sm;
    float* Ks = Qs + TQ * LDQ;
    float* Vs = Ks + TK * LDQ;
    float* Ss = Vs + TK * LDQ;
    float* mrow = Ss + TQ * LDS_S;
    float* lrow = mrow + TQ;
    float* crow = lrow + TQ;

    int q0 = blockIdx.x * TQ;
    int h  = blockIdx.y;
    int b  = blockIdx.z;
    int tid = threadIdx.x;
    int tx = tid & 15, ty = tid >> 4;

    const float* Qb = Q + (size_t)b * SEQ * Dtot + h * HD;
    const float* Kb = K + (size_t)b * SEQ * Dtot + h * HD;
    const float* Vb = V + (size_t)b * SEQ * Dtot + h * HD;

    for (int i = tid; i < TQ * HD; i += 256) {
        int r = i / HD, c = i % HD;
        Qs[r * LDQ + c] = Qb[(size_t)(q0 + r) * Dtot + c];
    }
    if (tid < TQ) { mrow[tid] = -INFINITY; lrow[tid] = 0.f; }
    float acc[4][NG * 4];
#pragma unroll
    for (int i = 0; i < 4; i++)
#pragma unroll
        for (int j = 0; j < NG * 4; j++) acc[i][j] = 0.f;
    __syncthreads();

    for (int k0 = 0; k0 < SEQ; k0 += TK) {
        if (MASK == 0) {
            if (k0 > q0 + 63 + 256 || k0 + 63 < q0 - 256) continue;
        }
        for (int i = tid; i < TK * HD; i += 256) {
            int r = i / HD, c = i % HD;
            Ks[r * LDQ + c] = Kb[(size_t)(k0 + r) * Dtot + c];
            Vs[r * LDQ + c] = Vb[(size_t)(k0 + r) * Dtot + c];
        }
        __syncthreads();

        float sacc[4][4];
#pragma unroll
        for (int i = 0; i < 4; i++)
#pragma unroll
            for (int j = 0; j < 4; j++) sacc[i][j] = 0.f;
        for (int kk = 0; kk < HD; kk++) {
            float a[4], bb[4];
#pragma unroll
            for (int i = 0; i < 4; i++) a[i] = Qs[(ty * 4 + i) * LDQ + kk];
#pragma unroll
            for (int j = 0; j < 4; j++) bb[j] = Ks[(tx * 4 + j) * LDQ + kk];
#pragma unroll
            for (int i = 0; i < 4; i++)
#pragma unroll
                for (int j = 0; j < 4; j++) sacc[i][j] += a[i] * bb[j];
        }
#pragma unroll
        for (int i = 0; i < 4; i++) {
            int gi_ = q0 + ty * 4 + i;
#pragma unroll
            for (int j = 0; j < 4; j++) {
                int gj = k0 + tx * 4 + j;
                float sv = sacc[i][j] * scale;
                bool ok;
                if      (MASK == 0) { int dd = gi_ - gj; ok = (dd <= 256 && dd >= -256); }
                else if (MASK == 1) { int dd = gi_ - gj; ok = (dd <= 256 && dd >= -256) || ((gj & 15) == 0); }
                else if (MASK == 2) { ok = is_global_pos(gi_) || is_global_pos(gj); }
                else ok = true;
                Ss[(ty * 4 + i) * LDS_S + tx * 4 + j] = ok ? sv : -1e9f;
            }
        }
        __syncthreads();

        if (tid < TQ) {
            float mo = mrow[tid];
            float mx = mo;
            float* srow = Ss + tid * LDS_S;
            for (int j = 0; j < TK; j++) mx = fmaxf(mx, srow[j]);
            float cf = expf(mo - mx);
            float sum = 0.f;
            for (int j = 0; j < TK; j++) {
                float p = expf(srow[j] - mx);
                srow[j] = p;
                sum += p;
            }
            mrow[tid] = mx;
            lrow[tid] = lrow[tid] * cf + sum;
            crow[tid] = cf;
        }
        __syncthreads();

#pragma unroll
        for (int i = 0; i < 4; i++) {
            float cf = crow[ty * 4 + i];
#pragma unroll
            for (int j = 0; j < NG * 4; j++) acc[i][j] *= cf;
        }
        for (int kk = 0; kk < TK; kk++) {
            float p[4];
#pragma unroll
            for (int i = 0; i < 4; i++) p[i] = Ss[(ty * 4 + i) * LDS_S + kk];
#pragma unroll
            for (int g = 0; g < NG; g++) {
#pragma unroll
                for (int j = 0; j < 4; j++) {
                    float vv = Vs[kk * LDQ + g * 64 + tx * 4 + j];
#pragma unroll
                    for (int i = 0; i < 4; i++) acc[i][g * 4 + j] += p[i] * vv;
                }
            }
        }
        __syncthreads();
    }

#pragma unroll
    for (int i = 0; i < 4; i++) {
        float inv = 1.0f / lrow[ty * 4 + i];
        size_t base = (size_t)(b * SEQ + q0 + ty * 4 + i) * Dtot + h * HD;
#pragma unroll
        for (int g = 0; g < NG; g++)
#pragma unroll
            for (int j = 0; j < 4; j++)
                O[base + g * 64 + tx * 4 + j] = acc[i][g * 4 + j] * inv;
    }
}

// -------------------- coupling ---------------------------------------------
__global__ void coupling_kernel(const float* __restrict__ feat,
                                const float* __restrict__ cat_,
                                float* __restrict__ out) {
    int idx = blockIdx.x * blockDim.x + threadIdx.x;
    if (idx >= MROWS * D_MODEL) return;
    int m = idx >> 9, d = idx & 511;
    float s = 0.f;
#pragma unroll
    for (int l = 0; l < 3; l++)
        s += feat[(size_t)l * MROWS * D_MODEL + idx] + cat_[(size_t)m * 1536 + l * 512 + d];
    out[idx] = s * (1.0f / 3.0f);
}

// -------------------- layernorm --------------------------------------------
__global__ __launch_bounds__(256)
void ln_kernel(const float* __restrict__ in, const float* __restrict__ g,
               const float* __restrict__ b, float* __restrict__ out) {
    __shared__ float red[256];
    int row = blockIdx.x;
    int tid = threadIdx.x;
    const float* xr = in + (size_t)row * D_MODEL;
    float v0 = xr[tid], v1 = xr[tid + 256];
    red[tid] = v0 + v1;
    __syncthreads();
    for (int o = 128; o > 0; o >>= 1) {
        if (tid < o) red[tid] += red[tid + o];
        __syncthreads();
    }
    float mu = red[0] * (1.0f / 512.0f);
    __syncthreads();
    float d0 = v0 - mu, d1 = v1 - mu;
    red[tid] = d0 * d0 + d1 * d1;
    __syncthreads();
    for (int o = 128; o > 0; o >>= 1) {
        if (tid < o) red[tid] += red[tid + o];
        __syncthreads();
    }
    float var = red[0] * (1.0f / 512.0f);
    float inv = rsqrtf(var + 1e-5f);
    out[(size_t)row * D_MODEL + tid]       = d0 * inv * g[tid] + b[tid];
    out[(size_t)row * D_MODEL + tid + 256] = d1 * inv * g[tid + 256] + b[tid + 256];
}

// -------------------- host side --------------------------------------------
static void gemm_big(const float* A, int lda, const float* W, const float* bias,
                     const float* res, int ldres,
                     float* C, int ldc, int M, int N, int K) {
    dim3 grid(N / 128, M / 128);
    gemm128_kernel<<<grid, 256>>>(A, lda, W, bias, res, ldres, C, ldc, M, N, K);
}

static void gemm_small(const float* A, int lda, const float* W, const float* bias,
                       const float* pos, int posP,
                       float* C, int ldc, int M, int N, int K) {
    dim3 grid(N / 64, M / 64);
    gemm64_kernel<<<grid, 256>>>(A, lda, W, bias, pos, posP, C, ldc, M, N, K);
}

extern "C" void kernel_launch(void* const* d_in, const int* in_sizes, int n_in,
                              void* d_out, int out_size) {
    const float* x      = (const float*)d_in[0];
    const float* proj_w = (const float*)d_in[1];
    const float* proj_b = (const float*)d_in[2];
    const float* pos_e  = (const float*)d_in[3];
    const float* wq     = (const float*)d_in[4];
    const float* bq     = (const float*)d_in[5];
    const float* wk     = (const float*)d_in[6];
    const float* bk     = (const float*)d_in[7];
    const float* wv     = (const float*)d_in[8];
    const float* bv     = (const float*)d_in[9];
    const float* wo     = (const float*)d_in[10];
    const float* bo     = (const float*)d_in[11];
    const float* fin_w  = (const float*)d_in[12];
    const float* fin_b  = (const float*)d_in[13];
    const float* fout_w = (const float*)d_in[14];
    const float* fout_b = (const float*)d_in[15];
    const float* outp_w = (const float*)d_in[16];
    const float* outp_b = (const float*)d_in[17];
    const float* ln_g   = (const float*)d_in[18];
    const float* ln_b   = (const float*)d_in[19];
    float* out = (float*)d_out;

    float *feat, *cat_, *q, *k, *v, *t1, *t2, *pool, *fp;
    cudaGetSymbolAddress((void**)&feat, g_feat);
    cudaGetSymbolAddress((void**)&cat_, g_cat);
    cudaGetSymbolAddress((void**)&q,    g_q);
    cudaGetSymbolAddress((void**)&k,    g_k);
    cudaGetSymbolAddress((void**)&v,    g_v);
    cudaGetSymbolAddress((void**)&t1,   g_t1);
    cudaGetSymbolAddress((void**)&t2,   g_t2);
    cudaGetSymbolAddress((void**)&pool, g_pool);
    cudaGetSymbolAddress((void**)&fp,   g_fp);

    const int SMEM_LVL = (3 * 64 * 65 + 64 * 65 + 3 * 64) * 4;
    const int SMEM_FUS = (3 * 64 * 193 + 64 * 65 + 3 * 64) * 4;
    cudaFuncSetAttribute((const void*)flash_kernel<64, 0>, cudaFuncAttributeMaxDynamicSharedMemorySize, SMEM_LVL);
    cudaFuncSetAttribute((const void*)flash_kernel<64, 1>, cudaFuncAttributeMaxDynamicSharedMemorySize, SMEM_LVL);
    cudaFuncSetAttribute((const void*)flash_kernel<64, 2>, cudaFuncAttributeMaxDynamicSharedMemorySize, SMEM_LVL);
    cudaFuncSetAttribute((const void*)flash_kernel<192, 3>, cudaFuncAttributeMaxDynamicSharedMemorySize, SMEM_FUS);

    const int POOLP[3] = {512, 128, 32};
    dim3 fgrid(SEQ / 64, NHEADS, BATCH);

    for (int l = 0; l < 3; l++) {
        int P = POOLP[l];
        int r = SEQ / P;
        int BP = BATCH * P;
        pool_kernel<<<(BP * D_MODEL + 255) / 256, 256>>>(x, pool, P, r);
        gemm_small(pool, D_MODEL, proj_w + (size_t)l * D_MODEL * D_MODEL,
                   proj_b + (size_t)l * D_MODEL,
                   pos_e + (size_t)l * 10000 * D_MODEL, P,
                   fp, D_MODEL, BP, D_MODEL, D_MODEL);
        float* fl = feat + (size_t)l * MROWS * D_MODEL;
        interp_kernel<<<(MROWS * D_MODEL + 255) / 256, 256>>>(fp, fl, P);
        gemm_big(fl, D_MODEL, wq + (size_t)l * D_MODEL * D_MODEL, bq + (size_t)l * D_MODEL,
                 nullptr, 0, q, D_MODEL, MROWS, D_MODEL, D_MODEL);
        gemm_big(fl, D_MODEL, wk + (size_t)l * D_MODEL * D_MODEL, bk + (size_t)l * D_MODEL,
                 nullptr, 0, k, D_MODEL, MROWS, D_MODEL, D_MODEL);
        gemm_big(fl, D_MODEL, wv + (size_t)l * D_MODEL * D_MODEL, bv + (size_t)l * D_MODEL,
                 nullptr, 0, v, D_MODEL, MROWS, D_MODEL, D_MODEL);
        float scale = 0.125f;
        if (l == 0)
            flash_kernel<64, 0><<<fgrid, 256, SMEM_LVL>>>(q, k, v, t1, D_MODEL, scale);
        else if (l == 1)
            flash_kernel<64, 1><<<fgrid, 256, SMEM_LVL>>>(q, k, v, t1, D_MODEL, scale);
        else
            flash_kernel<64, 2><<<fgrid, 256, SMEM_LVL>>>(q, k, v, t1, D_MODEL, scale);
        gemm_big(t1, D_MODEL, wo + (size_t)l * D_MODEL * D_MODEL, bo + (size_t)l * D_MODEL,
                 nullptr, 0, cat_ + (size_t)l * D_MODEL, 1536, MROWS, D_MODEL, D_MODEL);
    }

    coupling_kernel<<<(MROWS * D_MODEL + 255) / 256, 256>>>(feat, cat_, out + (size_t)MROWS * D_MODEL);

    gemm_big(cat_, 1536, fin_w,                           fin_b,        nullptr, 0, q, 1536, MROWS, 1536, 1536);
    gemm_big(cat_, 1536, fin_w + (size_t)1536 * 1536,     fin_b + 1536, nullptr, 0, k, 1536, MROWS, 1536, 1536);
    gemm_big(cat_, 1536, fin_w + (size_t)2 * 1536 * 1536, fin_b + 3072, nullptr, 0, v, 1536, MROWS, 1536, 1536);
    flash_kernel<192, 3><<<fgrid, 256, SMEM_FUS>>>(q, k, v, t1, 1536, 1.0f / sqrtf(192.0f));
    gemm_big(t1, 1536, fout_w, fout_b, nullptr, 0, t2, 1536, MROWS, 1536, 1536);
    gemm_big(t2, 1536, outp_w, outp_b, x, D_MODEL, t1, D_MODEL, MROWS, D_MODEL, 1536);
    ln_kernel<<<MROWS, 256>>>(t1, ln_g, ln_b, out);
}

// round 4
// speedup vs baseline: 1.6195x; 1.2565x over previous
#include <cuda_runtime.h>
#include <math.h>

// ---------------------------------------------------------------------------
// HierarchicalReversibleAttention — R4: tf32 mma.sync GEMM (tensor cores)
// ---------------------------------------------------------------------------

#define D_MODEL 512
#define SEQ     2048
#define BATCH   2
#define MROWS   (BATCH * SEQ)   // 4096
#define NHEADS  8

// -------------------- device scratch (static, no allocation) ---------------
__device__ __align__(16) float g_feat[(size_t)3 * MROWS * D_MODEL];
__device__ __align__(16) float g_cat [(size_t)MROWS * 1536];
__device__ __align__(16) float g_q   [(size_t)MROWS * 1536];
__device__ __align__(16) float g_k   [(size_t)MROWS * 1536];
__device__ __align__(16) float g_v   [(size_t)MROWS * 1536];
__device__ __align__(16) float g_t1  [(size_t)MROWS * 1536];
__device__ __align__(16) float g_t2  [(size_t)MROWS * 1536];
__device__ __align__(16) float g_pool[(size_t)BATCH * 512 * D_MODEL];
__device__ __align__(16) float g_fp  [(size_t)BATCH * 512 * D_MODEL];

// -------------------- helpers ----------------------------------------------
__device__ __forceinline__ bool is_global_pos(int j) {
    return (j == 2047) || ((j % 66 == 0) && (j <= 1980));
}

__device__ __forceinline__ unsigned f2tf32(float f) {
    unsigned u;
    asm("cvt.rna.tf32.f32 %0, %1;" : "=r"(u) : "f"(f));
    return u;
}

__device__ __forceinline__ void mma_tf32(float* c, const unsigned* a, const unsigned* b) {
    asm volatile(
        "mma.sync.aligned.m16n8k8.row.col.f32.tf32.tf32.f32 "
        "{%0,%1,%2,%3}, {%4,%5,%6,%7}, {%8,%9}, {%0,%1,%2,%3};"
        : "+f"(c[0]), "+f"(c[1]), "+f"(c[2]), "+f"(c[3])
        : "r"(a[0]), "r"(a[1]), "r"(a[2]), "r"(a[3]), "r"(b[0]), "r"(b[1]));
}

// -------------------- pooling ----------------------------------------------
__global__ void pool_kernel(const float* __restrict__ x, float* __restrict__ out,
                            int P, int r) {
    int idx = blockIdx.x * blockDim.x + threadIdx.x;
    int total = BATCH * P * D_MODEL;
    if (idx >= total) return;
    int d = idx & (D_MODEL - 1);
    int p = (idx >> 9) % P;
    int b = idx / (D_MODEL * P);
    const float* src = x + ((size_t)b * SEQ + (size_t)p * r) * D_MODEL + d;
    float s = 0.f;
    for (int t = 0; t < r; t++) s += src[(size_t)t * D_MODEL];
    out[idx] = s * (1.0f / (float)r);
}

// -------------------- linear interpolation (upsample) ----------------------
__global__ void interp_kernel(const float* __restrict__ in, float* __restrict__ out,
                              int P) {
    int idx = blockIdx.x * blockDim.x + threadIdx.x;
    if (idx >= MROWS * D_MODEL) return;
    int d = idx & (D_MODEL - 1);
    int s = (idx >> 9) & (SEQ - 1);
    int b = idx >> 20;
    float scale = (float)P / (float)SEQ;
    float src = ((float)s + 0.5f) * scale - 0.5f;
    float flr = floorf(src);
    float f = src - flr;
    int i0 = (int)flr;
    int a = i0 < 0 ? 0 : (i0 > P - 1 ? P - 1 : i0);
    int c = (i0 + 1) < 0 ? 0 : ((i0 + 1) > P - 1 ? P - 1 : i0 + 1);
    const float* base = in + (size_t)b * P * D_MODEL + d;
    out[idx] = (1.0f - f) * base[(size_t)a * D_MODEL] + f * base[(size_t)c * D_MODEL];
}

// -------------------- small GEMM (64x64, for proj M<128) -------------------
__global__ __launch_bounds__(256)
void gemm64_kernel(const float* __restrict__ A, int lda,
                   const float* __restrict__ W,
                   const float* __restrict__ bias,
                   const float* __restrict__ pos, int posP,
                   float* __restrict__ C, int ldc,
                   int M, int N, int K) {
    const int BM = 64, BN = 64, BK = 16;
    __shared__ float As[BK][BM + 1];
    __shared__ float Ws[BK][BN + 1];
    int bm = blockIdx.y * BM;
    int bn = blockIdx.x * BN;
    int tid = threadIdx.x;
    int tx = tid & 15, ty = tid >> 4;

    float acc[4][4];
#pragma unroll
    for (int i = 0; i < 4; i++)
#pragma unroll
        for (int j = 0; j < 4; j++) acc[i][j] = 0.f;

    for (int k0 = 0; k0 < K; k0 += BK) {
#pragma unroll
        for (int it = 0; it < 4; it++) {
            int i = tid + it * 256;
            int r = i >> 4, c = i & 15;
            As[c][r] = A[(size_t)(bm + r) * lda + k0 + c];
        }
#pragma unroll
        for (int it = 0; it < 4; it++) {
            int i = tid + it * 256;
            int r = i >> 4, c = i & 15;
            Ws[c][r] = W[(size_t)(bn + r) * K + k0 + c];
        }
        __syncthreads();
#pragma unroll
        for (int kk = 0; kk < BK; kk++) {
            float a[4], b[4];
#pragma unroll
            for (int i = 0; i < 4; i++) a[i] = As[kk][ty * 4 + i];
#pragma unroll
            for (int j = 0; j < 4; j++) b[j] = Ws[kk][tx * 4 + j];
#pragma unroll
            for (int i = 0; i < 4; i++)
#pragma unroll
                for (int j = 0; j < 4; j++) acc[i][j] += a[i] * b[j];
        }
        __syncthreads();
    }
#pragma unroll
    for (int i = 0; i < 4; i++) {
        int m = bm + ty * 4 + i;
#pragma unroll
        for (int j = 0; j < 4; j++) {
            int n = bn + tx * 4 + j;
            float v = acc[i][j];
            if (bias) v += bias[n];
            if (pos)  v += pos[(size_t)(m % posP) * N + n];
            C[(size_t)m * ldc + n] = v;
        }
    }
}

// -------------------- tf32 tensor-core GEMM: 128x128x16 --------------------
// C = A @ W^T (+bias)(+res).  A:[M,K] lda, W:[N,K], C:[M,N] ldc.
// M,N % 128 == 0, K % 16 == 0. 8 warps: 2(m) x 4(n), warp tile 64x32.
#define TS 136   // k-row stride (words); 136 mod 32 = 8
__device__ __forceinline__ int swz(int k, int col) {
    // XOR swizzle: spreads the 4 kq-groups across banks; verified conflict-free
    return k * TS + (col ^ (((k >> 2) & 3) << 3));
}

__global__ __launch_bounds__(256)
void gemm_tf32_kernel(const float* __restrict__ A, int lda,
                      const float* __restrict__ W,
                      const float* __restrict__ bias,
                      const float* __restrict__ res, int ldres,
                      float* __restrict__ C, int ldc,
                      int M, int N, int K) {
    __shared__ unsigned As[16 * TS];
    __shared__ unsigned Ws[16 * TS];

    int bm = blockIdx.y * 128;
    int bn = blockIdx.x * 128;
    int tid = threadIdx.x;
    int warp = tid >> 5, lane = tid & 31;
    int wm = (warp >> 2) * 64;       // 0 or 64
    int wn = (warp & 3) * 32;        // 0,32,64,96
    int gid = lane >> 2;             // 0..7
    int tig = lane & 3;              // 0..3

    int r0 = tid >> 2;               // 0..63
    int kq = (tid & 3) << 2;         // 0,4,8,12

    float c[4][4][4];
#pragma unroll
    for (int i = 0; i < 4; i++)
#pragma unroll
        for (int j = 0; j < 4; j++)
#pragma unroll
            for (int e = 0; e < 4; e++) c[i][j][e] = 0.f;

    const float* Ap0 = &A[(size_t)(bm + r0) * lda + kq];
    const float* Ap1 = &A[(size_t)(bm + r0 + 64) * lda + kq];
    const float* Wp0 = &W[(size_t)(bn + r0) * K + kq];
    const float* Wp1 = &W[(size_t)(bn + r0 + 64) * K + kq];

    float4 ra0 = *(const float4*)Ap0;
    float4 ra1 = *(const float4*)Ap1;
    float4 rw0 = *(const float4*)Wp0;
    float4 rw1 = *(const float4*)Wp1;

    for (int k0 = 0; k0 < K; k0 += 16) {
        // store prefetched tile to smem (cvt to tf32 bits)
        As[swz(kq + 0, r0)]      = f2tf32(ra0.x);
        As[swz(kq + 1, r0)]      = f2tf32(ra0.y);
        As[swz(kq + 2, r0)]      = f2tf32(ra0.z);
        As[swz(kq + 3, r0)]      = f2tf32(ra0.w);
        As[swz(kq + 0, r0 + 64)] = f2tf32(ra1.x);
        As[swz(kq + 1, r0 + 64)] = f2tf32(ra1.y);
        As[swz(kq + 2, r0 + 64)] = f2tf32(ra1.z);
        As[swz(kq + 3, r0 + 64)] = f2tf32(ra1.w);
        Ws[swz(kq + 0, r0)]      = f2tf32(rw0.x);
        Ws[swz(kq + 1, r0)]      = f2tf32(rw0.y);
        Ws[swz(kq + 2, r0)]      = f2tf32(rw0.z);
        Ws[swz(kq + 3, r0)]      = f2tf32(rw0.w);
        Ws[swz(kq + 0, r0 + 64)] = f2tf32(rw1.x);
        Ws[swz(kq + 1, r0 + 64)] = f2tf32(rw1.y);
        Ws[swz(kq + 2, r0 + 64)] = f2tf32(rw1.z);
        Ws[swz(kq + 3, r0 + 64)] = f2tf32(rw1.w);
        __syncthreads();

        // prefetch next tile into registers (overlaps with mma phase)
        if (k0 + 16 < K) {
            ra0 = *(const float4*)(Ap0 + k0 + 16);
            ra1 = *(const float4*)(Ap1 + k0 + 16);
            rw0 = *(const float4*)(Wp0 + k0 + 16);
            rw1 = *(const float4*)(Wp1 + k0 + 16);
        }

#pragma unroll
        for (int kk = 0; kk < 16; kk += 8) {
            unsigned a[4][4], b[4][2];
#pragma unroll
            for (int i = 0; i < 4; i++) {
                int m = wm + i * 16 + gid;
                a[i][0] = As[swz(kk + tig,     m)];
                a[i][1] = As[swz(kk + tig,     m + 8)];
                a[i][2] = As[swz(kk + tig + 4, m)];
                a[i][3] = As[swz(kk + tig + 4, m + 8)];
            }
#pragma unroll
            for (int j = 0; j < 4; j++) {
                int n = wn + j * 8 + gid;
                b[j][0] = Ws[swz(kk + tig,     n)];
                b[j][1] = Ws[swz(kk + tig + 4, n)];
            }
#pragma unroll
            for (int i = 0; i < 4; i++)
#pragma unroll
                for (int j = 0; j < 4; j++)
                    mma_tf32(c[i][j], a[i], b[j]);
        }
        __syncthreads();
    }

    // -------- epilogue --------
#pragma unroll
    for (int i = 0; i < 4; i++) {
        int row = bm + wm + i * 16 + gid;
#pragma unroll
        for (int j = 0; j < 4; j++) {
            int col = bn + wn + j * 8 + tig * 2;
            float v00 = c[i][j][0], v01 = c[i][j][1];
            float v10 = c[i][j][2], v11 = c[i][j][3];
            if (bias) {
                float b0 = bias[col], b1 = bias[col + 1];
                v00 += b0; v01 += b1; v10 += b0; v11 += b1;
            }
            if (res) {
                const float* rr0 = &res[(size_t)row * ldres + col];
                const float* rr1 = &res[(size_t)(row + 8) * ldres + col];
                v00 += rr0[0]; v01 += rr0[1];
                v10 += rr1[0]; v11 += rr1[1];
            }
            float2 s0; s0.x = v00; s0.y = v01;
            float2 s1; s1.x = v10; s1.y = v11;
            *(float2*)&C[(size_t)row * ldc + col] = s0;
            *(float2*)&C[(size_t)(row + 8) * ldc + col] = s1;
        }
    }
}

// -------------------- flash attention --------------------------------------
template<int HD, int MASK>
__global__ __launch_bounds__(256)
void flash_kernel(const float* __restrict__ Q, const float* __restrict__ K,
                  const float* __restrict__ V, float* __restrict__ O,
                  int Dtot, float scale) {
    const int TQ = 64, TK = 64;
    const int NG = HD / 64;
    const int LDQ = HD + 1;
    const int LDS_S = TK + 1;
    extern __shared__ float sm[];
    float* Qs = sm;
    float* Ks = Qs + TQ * LDQ;
    float* Vs = Ks + TK * LDQ;
    float* Ss = Vs + TK * LDQ;
    float* mrow = Ss + TQ * LDS_S;
    float* lrow = mrow + TQ;
    float* crow = lrow + TQ;

    int q0 = blockIdx.x * TQ;
    int h  = blockIdx.y;
    int b  = blockIdx.z;
    int tid = threadIdx.x;
    int tx = tid & 15, ty = tid >> 4;

    const float* Qb = Q + (size_t)b * SEQ * Dtot + h * HD;
    const float* Kb = K + (size_t)b * SEQ * Dtot + h * HD;
    const float* Vb = V + (size_t)b * SEQ * Dtot + h * HD;

    for (int i = tid; i < TQ * HD; i += 256) {
        int r = i / HD, c = i % HD;
        Qs[r * LDQ + c] = Qb[(size_t)(q0 + r) * Dtot + c];
    }
    if (tid < TQ) { mrow[tid] = -INFINITY; lrow[tid] = 0.f; }
    float acc[4][NG * 4];
#pragma unroll
    for (int i = 0; i < 4; i++)
#pragma unroll
        for (int j = 0; j < NG * 4; j++) acc[i][j] = 0.f;
    __syncthreads();

    for (int k0 = 0; k0 < SEQ; k0 += TK) {
        if (MASK == 0) {
            if (k0 > q0 + 63 + 256 || k0 + 63 < q0 - 256) continue;
        }
        for (int i = tid; i < TK * HD; i += 256) {
            int r = i / HD, c = i % HD;
            Ks[r * LDQ + c] = Kb[(size_t)(k0 + r) * Dtot + c];
            Vs[r * LDQ + c] = Vb[(size_t)(k0 + r) * Dtot + c];
        }
        __syncthreads();

        float sacc[4][4];
#pragma unroll
        for (int i = 0; i < 4; i++)
#pragma unroll
            for (int j = 0; j < 4; j++) sacc[i][j] = 0.f;
        for (int kk = 0; kk < HD; kk++) {
            float a[4], bb[4];
#pragma unroll
            for (int i = 0; i < 4; i++) a[i] = Qs[(ty * 4 + i) * LDQ + kk];
#pragma unroll
            for (int j = 0; j < 4; j++) bb[j] = Ks[(tx * 4 + j) * LDQ + kk];
#pragma unroll
            for (int i = 0; i < 4; i++)
#pragma unroll
                for (int j = 0; j < 4; j++) sacc[i][j] += a[i] * bb[j];
        }
#pragma unroll
        for (int i = 0; i < 4; i++) {
            int gi_ = q0 + ty * 4 + i;
#pragma unroll
            for (int j = 0; j < 4; j++) {
                int gj = k0 + tx * 4 + j;
                float sv = sacc[i][j] * scale;
                bool ok;
                if      (MASK == 0) { int dd = gi_ - gj; ok = (dd <= 256 && dd >= -256); }
                else if (MASK == 1) { int dd = gi_ - gj; ok = (dd <= 256 && dd >= -256) || ((gj & 15) == 0); }
                else if (MASK == 2) { ok = is_global_pos(gi_) || is_global_pos(gj); }
                else ok = true;
                Ss[(ty * 4 + i) * LDS_S + tx * 4 + j] = ok ? sv : -1e9f;
            }
        }
        __syncthreads();

        if (tid < TQ) {
            float mo = mrow[tid];
            float mx = mo;
            float* srow = Ss + tid * LDS_S;
            for (int j = 0; j < TK; j++) mx = fmaxf(mx, srow[j]);
            float cf = expf(mo - mx);
            float sum = 0.f;
            for (int j = 0; j < TK; j++) {
                float p = expf(srow[j] - mx);
                srow[j] = p;
                sum += p;
            }
            mrow[tid] = mx;
            lrow[tid] = lrow[tid] * cf + sum;
            crow[tid] = cf;
        }
        __syncthreads();

#pragma unroll
        for (int i = 0; i < 4; i++) {
            float cf = crow[ty * 4 + i];
#pragma unroll
            for (int j = 0; j < NG * 4; j++) acc[i][j] *= cf;
        }
        for (int kk = 0; kk < TK; kk++) {
            float p[4];
#pragma unroll
            for (int i = 0; i < 4; i++) p[i] = Ss[(ty * 4 + i) * LDS_S + kk];
#pragma unroll
            for (int g = 0; g < NG; g++) {
#pragma unroll
                for (int j = 0; j < 4; j++) {
                    float vv = Vs[kk * LDQ + g * 64 + tx * 4 + j];
#pragma unroll
                    for (int i = 0; i < 4; i++) acc[i][g * 4 + j] += p[i] * vv;
                }
            }
        }
        __syncthreads();
    }

#pragma unroll
    for (int i = 0; i < 4; i++) {
        float inv = 1.0f / lrow[ty * 4 + i];
        size_t base = (size_t)(b * SEQ + q0 + ty * 4 + i) * Dtot + h * HD;
#pragma unroll
        for (int g = 0; g < NG; g++)
#pragma unroll
            for (int j = 0; j < 4; j++)
                O[base + g * 64 + tx * 4 + j] = acc[i][g * 4 + j] * inv;
    }
}

// -------------------- coupling ---------------------------------------------
__global__ void coupling_kernel(const float* __restrict__ feat,
                                const float* __restrict__ cat_,
                                float* __restrict__ out) {
    int idx = blockIdx.x * blockDim.x + threadIdx.x;
    if (idx >= MROWS * D_MODEL) return;
    int m = idx >> 9, d = idx & 511;
    float s = 0.f;
#pragma unroll
    for (int l = 0; l < 3; l++)
        s += feat[(size_t)l * MROWS * D_MODEL + idx] + cat_[(size_t)m * 1536 + l * 512 + d];
    out[idx] = s * (1.0f / 3.0f);
}

// -------------------- layernorm --------------------------------------------
__global__ __launch_bounds__(256)
void ln_kernel(const float* __restrict__ in, const float* __restrict__ g,
               const float* __restrict__ b, float* __restrict__ out) {
    __shared__ float red[256];
    int row = blockIdx.x;
    int tid = threadIdx.x;
    const float* xr = in + (size_t)row * D_MODEL;
    float v0 = xr[tid], v1 = xr[tid + 256];
    red[tid] = v0 + v1;
    __syncthreads();
    for (int o = 128; o > 0; o >>= 1) {
        if (tid < o) red[tid] += red[tid + o];
        __syncthreads();
    }
    float mu = red[0] * (1.0f / 512.0f);
    __syncthreads();
    float d0 = v0 - mu, d1 = v1 - mu;
    red[tid] = d0 * d0 + d1 * d1;
    __syncthreads();
    for (int o = 128; o > 0; o >>= 1) {
        if (tid < o) red[tid] += red[tid + o];
        __syncthreads();
    }
    float var = red[0] * (1.0f / 512.0f);
    float inv = rsqrtf(var + 1e-5f);
    out[(size_t)row * D_MODEL + tid]       = d0 * inv * g[tid] + b[tid];
    out[(size_t)row * D_MODEL + tid + 256] = d1 * inv * g[tid + 256] + b[tid + 256];
}

// -------------------- host side --------------------------------------------
static void gemm_big(const float* A, int lda, const float* W, const float* bias,
                     const float* res, int ldres,
                     float* C, int ldc, int M, int N, int K) {
    dim3 grid(N / 128, M / 128);
    gemm_tf32_kernel<<<grid, 256>>>(A, lda, W, bias, res, ldres, C, ldc, M, N, K);
}

static void gemm_small(const float* A, int lda, const float* W, const float* bias,
                       const float* pos, int posP,
                       float* C, int ldc, int M, int N, int K) {
    dim3 grid(N / 64, M / 64);
    gemm64_kernel<<<grid, 256>>>(A, lda, W, bias, pos, posP, C, ldc, M, N, K);
}

extern "C" void kernel_launch(void* const* d_in, const int* in_sizes, int n_in,
                              void* d_out, int out_size) {
    const float* x      = (const float*)d_in[0];
    const float* proj_w = (const float*)d_in[1];
    const float* proj_b = (const float*)d_in[2];
    const float* pos_e  = (const float*)d_in[3];
    const float* wq     = (const float*)d_in[4];
    const float* bq     = (const float*)d_in[5];
    const float* wk     = (const float*)d_in[6];
    const float* bk     = (const float*)d_in[7];
    const float* wv     = (const float*)d_in[8];
    const float* bv     = (const float*)d_in[9];
    const float* wo     = (const float*)d_in[10];
    const float* bo     = (const float*)d_in[11];
    const float* fin_w  = (const float*)d_in[12];
    const float* fin_b  = (const float*)d_in[13];
    const float* fout_w = (const float*)d_in[14];
    const float* fout_b = (const float*)d_in[15];
    const float* outp_w = (const float*)d_in[16];
    const float* outp_b = (const float*)d_in[17];
    const float* ln_g   = (const float*)d_in[18];
    const float* ln_b   = (const float*)d_in[19];
    float* out = (float*)d_out;

    float *feat, *cat_, *q, *k, *v, *t1, *t2, *pool, *fp;
    cudaGetSymbolAddress((void**)&feat, g_feat);
    cudaGetSymbolAddress((void**)&cat_, g_cat);
    cudaGetSymbolAddress((void**)&q,    g_q);
    cudaGetSymbolAddress((void**)&k,    g_k);
    cudaGetSymbolAddress((void**)&v,    g_v);
    cudaGetSymbolAddress((void**)&t1,   g_t1);
    cudaGetSymbolAddress((void**)&t2,   g_t2);
    cudaGetSymbolAddress((void**)&pool, g_pool);
    cudaGetSymbolAddress((void**)&fp,   g_fp);

    const int SMEM_LVL = (3 * 64 * 65 + 64 * 65 + 3 * 64) * 4;
    const int SMEM_FUS = (3 * 64 * 193 + 64 * 65 + 3 * 64) * 4;
    cudaFuncSetAttribute((const void*)flash_kernel<64, 0>, cudaFuncAttributeMaxDynamicSharedMemorySize, SMEM_LVL);
    cudaFuncSetAttribute((const void*)flash_kernel<64, 1>, cudaFuncAttributeMaxDynamicSharedMemorySize, SMEM_LVL);
    cudaFuncSetAttribute((const void*)flash_kernel<64, 2>, cudaFuncAttributeMaxDynamicSharedMemorySize, SMEM_LVL);
    cudaFuncSetAttribute((const void*)flash_kernel<192, 3>, cudaFuncAttributeMaxDynamicSharedMemorySize, SMEM_FUS);

    const int POOLP[3] = {512, 128, 32};
    dim3 fgrid(SEQ / 64, NHEADS, BATCH);

    for (int l = 0; l < 3; l++) {
        int P = POOLP[l];
        int r = SEQ / P;
        int BP = BATCH * P;
        pool_kernel<<<(BP * D_MODEL + 255) / 256, 256>>>(x, pool, P, r);
        gemm_small(pool, D_MODEL, proj_w + (size_t)l * D_MODEL * D_MODEL,
                   proj_b + (size_t)l * D_MODEL,
                   pos_e + (size_t)l * 10000 * D_MODEL, P,
                   fp, D_MODEL, BP, D_MODEL, D_MODEL);
        float* fl = feat + (size_t)l * MROWS * D_MODEL;
        interp_kernel<<<(MROWS * D_MODEL + 255) / 256, 256>>>(fp, fl, P);
        gemm_big(fl, D_MODEL, wq + (size_t)l * D_MODEL * D_MODEL, bq + (size_t)l * D_MODEL,
                 nullptr, 0, q, D_MODEL, MROWS, D_MODEL, D_MODEL);
        gemm_big(fl, D_MODEL, wk + (size_t)l * D_MODEL * D_MODEL, bk + (size_t)l * D_MODEL,
                 nullptr, 0, k, D_MODEL, MROWS, D_MODEL, D_MODEL);
        gemm_big(fl, D_MODEL, wv + (size_t)l * D_MODEL * D_MODEL, bv + (size_t)l * D_MODEL,
                 nullptr, 0, v, D_MODEL, MROWS, D_MODEL, D_MODEL);
        float scale = 0.125f;
        if (l == 0)
            flash_kernel<64, 0><<<fgrid, 256, SMEM_LVL>>>(q, k, v, t1, D_MODEL, scale);
        else if (l == 1)
            flash_kernel<64, 1><<<fgrid, 256, SMEM_LVL>>>(q, k, v, t1, D_MODEL, scale);
        else
            flash_kernel<64, 2><<<fgrid, 256, SMEM_LVL>>>(q, k, v, t1, D_MODEL, scale);
        gemm_big(t1, D_MODEL, wo + (size_t)l * D_MODEL * D_MODEL, bo + (size_t)l * D_MODEL,
                 nullptr, 0, cat_ + (size_t)l * D_MODEL, 1536, MROWS, D_MODEL, D_MODEL);
    }

    coupling_kernel<<<(MROWS * D_MODEL + 255) / 256, 256>>>(feat, cat_, out + (size_t)MROWS * D_MODEL);

    gemm_big(cat_, 1536, fin_w,                           fin_b,        nullptr, 0, q, 1536, MROWS, 1536, 1536);
    gemm_big(cat_, 1536, fin_w + (size_t)1536 * 1536,     fin_b + 1536, nullptr, 0, k, 1536, MROWS, 1536, 1536);
    gemm_big(cat_, 1536, fin_w + (size_t)2 * 1536 * 1536, fin_b + 3072, nullptr, 0, v, 1536, MROWS, 1536, 1536);
    flash_kernel<192, 3><<<fgrid, 256, SMEM_FUS>>>(q, k, v, t1, 1536, 1.0f / sqrtf(192.0f));
    gemm_big(t1, 1536, fout_w, fout_b, nullptr, 0, t2, 1536, MROWS, 1536, 1536);
    gemm_big(t2, 1536, outp_w, outp_b, x, D_MODEL, t1, D_MODEL, MROWS, D_MODEL, 1536);
    ln_kernel<<<MROWS, 256>>>(t1, ln_g, ln_b, out);
}